// round 4
// baseline (speedup 1.0000x reference)
#include <cuda_runtime.h>
#include <math.h>

// SPD log-map via Chebyshev + Paterson-Stockmeyer, degree 11, base W = T_4.
//
// X~ = (X-c)/d maps spectrum to [-1,1];
// log(x) = a0 + sum_{k=1}^{11} a_k T_k(t), a_k = 2(-1)^{k+1} beta^k/k.
// Fold via T_q(W) T_r = (T_{4q+r} + T_{4q-r})/2 into sum_{q=0}^{2} T_q(W) P_q,
// P_q elementwise combos of {I, X~, T2, T3}. Then
//   S = (P0 - P2) + W*(P1 + 2*W*P2)
// Matmuls (5): X*X (-> bound + T2 elementwise), T3, W=T4, M=W*P2, S=W*b1.
// All operands symmetric -> A rows read as contiguous float4 (A[i][k]=A[k][i]).
// 72 upper 8x4 tiles per matrix; pure-upper tiles mirror-stored as float4,
// diagonal-straddling tiles stored with element predication.

#define LDM      68
#define NTHREADS 96
#define NTILES   72      // 8x4 tiles intersecting the upper triangle
#define MATN     64
#define MATSZ    (MATN * MATN)
#define OUTSZ    2080

__device__ __forceinline__ void mm_tile8(const float* __restrict__ A,
                                         const float* __restrict__ B,
                                         int i0, int j0, float s[8][4])
{
    #pragma unroll
    for (int r = 0; r < 8; r++)
        #pragma unroll
        for (int c = 0; c < 4; c++) s[r][c] = 0.f;
    const float* Ap = A + i0;
    const float* Bp = B + j0;
    #pragma unroll 4
    for (int kk = 0; kk < MATN; kk++) {
        const float4 a0 = *(const float4*)(Ap + kk * LDM);      // A[i0..i0+3][kk]
        const float4 a1 = *(const float4*)(Ap + kk * LDM + 4);  // A[i0+4..i0+7][kk]
        const float4 bv = *(const float4*)(Bp + kk * LDM);
        const float av[8] = {a0.x, a0.y, a0.z, a0.w, a1.x, a1.y, a1.z, a1.w};
        #pragma unroll
        for (int r = 0; r < 8; r++) {
            s[r][0] += av[r] * bv.x;
            s[r][1] += av[r] * bv.y;
            s[r][2] += av[r] * bv.z;
            s[r][3] += av[r] * bv.w;
        }
    }
}

__device__ __forceinline__ void load_tile8(const float* __restrict__ M,
                                           int i0, int j0, float v[8][4])
{
    #pragma unroll
    for (int r = 0; r < 8; r++) {
        const float4 t = *(const float4*)(M + (i0 + r) * LDM + j0);
        v[r][0] = t.x; v[r][1] = t.y; v[r][2] = t.z; v[r][3] = t.w;
    }
}

__device__ __forceinline__ void store_tile8_sym(float* __restrict__ M,
                                                int i0, int j0, bool straddle,
                                                const float v[8][4])
{
    if (!straddle) {
        #pragma unroll
        for (int r = 0; r < 8; r++)
            *(float4*)(M + (i0 + r) * LDM + j0) =
                make_float4(v[r][0], v[r][1], v[r][2], v[r][3]);
        #pragma unroll
        for (int c = 0; c < 4; c++) {
            *(float4*)(M + (j0 + c) * LDM + i0) =
                make_float4(v[0][c], v[1][c], v[2][c], v[3][c]);
            *(float4*)(M + (j0 + c) * LDM + i0 + 4) =
                make_float4(v[4][c], v[5][c], v[6][c], v[7][c]);
        }
    } else {
        #pragma unroll
        for (int r = 0; r < 8; r++)
            #pragma unroll
            for (int c = 0; c < 4; c++) {
                const int i = i0 + r, j = j0 + c;
                if (i <= j) {
                    M[i * LDM + j] = v[r][c];
                    if (i < j) M[j * LDM + i] = v[r][c];
                }
            }
    }
}

__global__ void __launch_bounds__(NTHREADS)
spd_log_cheb_ps11_kernel(const float* __restrict__ xg, float* __restrict__ outg)
{
    extern __shared__ float sm[];
    float* Xs  = sm + 0 * MATN * LDM;   // X, then X~ (= T1)
    float* T2s = sm + 1 * MATN * LDM;
    float* T3s = sm + 2 * MATN * LDM;
    float* Ws  = sm + 3 * MATN * LDM;   // X*X, then W = T4
    float* B1  = sm + 4 * MATN * LDM;   // P2
    float* B2  = sm + 5 * MATN * LDM;   // b1
    float* rs  = sm + 6 * MATN * LDM;   // rowsums + maxima

    const int t = threadIdx.x;
    const float* X = xg + (size_t)blockIdx.x * MATSZ;

    // ---- load X ----
    for (int e = t; e < MATSZ; e += NTHREADS)
        Xs[(e >> 6) * LDM + (e & 63)] = X[e];
    __syncthreads();

    // ---- tile assignment: t < 72 owns 8x4 tile (bi, bj), bj >= 2*bi ----
    const bool active = (t < NTILES);
    int bi = 0, bj = 0;
    {
        int tt = active ? t : 0;
        while (tt >= 16 - 2 * bi) { tt -= 16 - 2 * bi; bi++; }
        bj = 2 * bi + tt;
    }
    const int i0 = bi * 8, j0 = bj * 4;
    const bool straddle = (bj <= 2 * bi + 1);

    // ---- matmul 1: X2 = X * X ----
    if (active) {
        float s[8][4];
        mm_tile8(Xs, Xs, i0, j0, s);
        store_tile8_sym(Ws, i0, j0, straddle, s);
    }
    __syncthreads();

    // ---- Gershgorin bounds (X and X^2) ----
    if (t < MATN) {
        float sa = 0.f, sb = 0.f;
        #pragma unroll
        for (int j = 0; j < MATN; j++) {
            sa += fabsf(Xs[t * LDM + j]);
            sb += fabsf(Ws[t * LDM + j]);
        }
        rs[t] = sa;
        rs[64 + t] = sb;
    }
    __syncthreads();
    if (t < 32) {
        float ma = fmaxf(rs[t], rs[t + 32]);
        float mb = fmaxf(rs[64 + t], rs[96 + t]);
        #pragma unroll
        for (int o = 16; o > 0; o >>= 1) {
            ma = fmaxf(ma, __shfl_xor_sync(0xffffffffu, ma, o));
            mb = fmaxf(mb, __shfl_xor_sync(0xffffffffu, mb, o));
        }
        if (t == 0) { rs[128] = ma; rs[129] = mb; }
    }
    __syncthreads();

    // ---- interval, beta, coefficients, PS fold (deg 11, base 4, q<=2) ----
    const float lo = 0.95f;
    float bmax = fminf(rs[128] * 1.0003f + 2e-3f, sqrtf(rs[129] * 1.001f) + 5e-3f);
    bmax = fmaxf(bmax, lo + 0.5f);
    const float cc     = 0.5f * (bmax + lo);
    const float dd     = 0.5f * (bmax - lo);
    const float inv_dd = 1.0f / dd;
    const float inv_d2 = inv_dd * inv_dd;
    const float ratio  = cc * inv_dd;
    const float beta   = ratio - sqrtf(ratio * ratio - 1.0f);

    float a[12];
    a[0] = logf(dd / (2.0f * beta));
    {
        float p = beta;
        a[1] = 2.f * p;
        #pragma unroll
        for (int k = 2; k <= 11; k++) { p = -p * beta; a[k] = 2.f * p / (float)k; }
    }
    float cf[3][4];
    #pragma unroll
    for (int q = 0; q < 3; q++)
        #pragma unroll
        for (int r = 0; r < 4; r++) cf[q][r] = 0.f;
    #pragma unroll
    for (int k = 11; k >= 4; k--) {
        const int q = k >> 2, r = k & 3;
        if (r > 0) { cf[q][r] = 2.f * a[k]; a[4 * q - r] -= a[k]; }
        else       { cf[q][0] = a[k]; }
    }
    #pragma unroll
    for (int r = 0; r < 4; r++) cf[0][r] = a[r];

    // ---- fused elementwise: T2 = (2X^2 - 4cX + 2c^2 I)/d^2 - I ; X~ = (X-c)/d ----
    const float t2diag = 2.f * cc * cc * inv_d2 - 1.f;
    for (int e = t; e < MATSZ; e += NTHREADS) {
        const int r = e >> 6, j = e & 63;
        const int idx = r * LDM + j;
        const float x  = Xs[idx];
        const float x2 = Ws[idx];
        const float dl = (r == j) ? 1.f : 0.f;
        T2s[idx] = (2.f * x2 - 4.f * cc * x) * inv_d2 + t2diag * dl;
        Xs[idx]  = (x - cc * dl) * inv_dd;
    }
    __syncthreads();

    // ---- matmul 2: T3 = 2 X~ T2 - X~ ----
    if (active) {
        float s[8][4], xt[8][4];
        mm_tile8(Xs, T2s, i0, j0, s);
        load_tile8(Xs, i0, j0, xt);
        float v[8][4];
        #pragma unroll
        for (int r = 0; r < 8; r++)
            #pragma unroll
            for (int c = 0; c < 4; c++) v[r][c] = 2.f * s[r][c] - xt[r][c];
        store_tile8_sym(T3s, i0, j0, straddle, v);
    }
    __syncthreads();

    // ---- matmul 3: W = T4 = 2 X~ T3 - T2 ; fused: P2 -> B1 ----
    if (active) {
        float s[8][4], xt[8][4], t2[8][4], t3[8][4];
        mm_tile8(Xs, T3s, i0, j0, s);
        load_tile8(Xs, i0, j0, xt);
        load_tile8(T2s, i0, j0, t2);
        load_tile8(T3s, i0, j0, t3);
        float w[8][4], p2[8][4];
        #pragma unroll
        for (int r = 0; r < 8; r++)
            #pragma unroll
            for (int c = 0; c < 4; c++) {
                w[r][c] = 2.f * s[r][c] - t2[r][c];
                const float dl = ((i0 + r) == (j0 + c)) ? 1.f : 0.f;
                p2[r][c] = cf[2][0] * dl + cf[2][1] * xt[r][c]
                         + cf[2][2] * t2[r][c] + cf[2][3] * t3[r][c];
            }
        store_tile8_sym(Ws, i0, j0, straddle, w);
        store_tile8_sym(B1, i0, j0, straddle, p2);
    }
    __syncthreads();

    // ---- matmul 4: M = W * P2 ; fused: b1 = P1 + 2M -> B2 ----
    if (active) {
        float s[8][4], xt[8][4], t2[8][4], t3[8][4];
        mm_tile8(Ws, B1, i0, j0, s);
        load_tile8(Xs, i0, j0, xt);
        load_tile8(T2s, i0, j0, t2);
        load_tile8(T3s, i0, j0, t3);
        float v[8][4];
        #pragma unroll
        for (int r = 0; r < 8; r++)
            #pragma unroll
            for (int c = 0; c < 4; c++) {
                const float dl = ((i0 + r) == (j0 + c)) ? 1.f : 0.f;
                v[r][c] = 2.f * s[r][c] + cf[1][0] * dl + cf[1][1] * xt[r][c]
                        + cf[1][2] * t2[r][c] + cf[1][3] * t3[r][c];
            }
        store_tile8_sym(B2, i0, j0, straddle, v);
    }
    __syncthreads();

    // ---- matmul 5: S = W * b1 + P0 - P2 -> output ----
    if (active) {
        float s[8][4], xt[8][4], t2[8][4], t3[8][4], p2[8][4];
        mm_tile8(Ws, B2, i0, j0, s);
        load_tile8(Xs, i0, j0, xt);
        load_tile8(T2s, i0, j0, t2);
        load_tile8(T3s, i0, j0, t3);
        load_tile8(B1, i0, j0, p2);
        float* o = outg + (size_t)blockIdx.x * OUTSZ;
        #pragma unroll
        for (int r = 0; r < 8; r++)
            #pragma unroll
            for (int c = 0; c < 4; c++) {
                const int i = i0 + r, j = j0 + c;
                if (i <= j) {
                    const float dl = (i == j) ? 1.f : 0.f;
                    const float val = s[r][c] - p2[r][c] + cf[0][0] * dl
                                    + cf[0][1] * xt[r][c] + cf[0][2] * t2[r][c]
                                    + cf[0][3] * t3[r][c];
                    o[i * MATN - (i * (i - 1)) / 2 + (j - i)] = val;
                }
            }
    }
}

extern "C" void kernel_launch(void* const* d_in, const int* in_sizes, int n_in,
                              void* d_out, int out_size)
{
    const float* x = (const float*)d_in[0];
    float* out = (float*)d_out;
    const int B = in_sizes[0] / MATSZ;

    const int smem_bytes = (6 * MATN * LDM + 132) * (int)sizeof(float);
    cudaFuncSetAttribute(spd_log_cheb_ps11_kernel,
                         cudaFuncAttributeMaxDynamicSharedMemorySize, smem_bytes);

    spd_log_cheb_ps11_kernel<<<B, NTHREADS, smem_bytes>>>(x, out);
}

// round 6
// speedup vs baseline: 1.2750x; 1.2750x over previous
#include <cuda_runtime.h>
#include <math.h>

// SPD log-map: Chebyshev deg-11 + Paterson-Stockmeyer (base W = T_4).
//   S = (P0 - P2) + W*(P1 + 2*W*P2),  P_q = elementwise combos of {I,X~,T2,T3}
// 5 matmuls: X*X (-> eigen bound + T2 elementwise), T3, W=T4, W*P2, W*b1.
// 8x4 register tiles over the upper triangle (72 tiles, 96 threads);
// A-operand rows read as contiguous float4 via symmetry (A[i][k]=A[k][i]).
// 4 smem matrix buffers (3 CTAs/SM): per-thread P1 and E0=P0-P2 tiles cached
// in registers at step 3; P2 overwrites Xs, b1 overwrites T3s.
// NOTE: every __syncthreads() is reached by ALL threads (no divergent barriers).

#define LDM      68
#define NTHREADS 96
#define NTILES   72
#define MATN     64
#define MATSZ    (MATN * MATN)
#define OUTSZ    2080

__device__ __forceinline__ void mm_tile8(const float* __restrict__ A,
                                         const float* __restrict__ B,
                                         int i0, int j0, float s[8][4])
{
    #pragma unroll
    for (int r = 0; r < 8; r++)
        #pragma unroll
        for (int c = 0; c < 4; c++) s[r][c] = 0.f;
    const float* Ap = A + i0;
    const float* Bp = B + j0;
    #pragma unroll 4
    for (int kk = 0; kk < MATN; kk++) {
        const float4 a0 = *(const float4*)(Ap + kk * LDM);
        const float4 a1 = *(const float4*)(Ap + kk * LDM + 4);
        const float4 bv = *(const float4*)(Bp + kk * LDM);
        const float av[8] = {a0.x, a0.y, a0.z, a0.w, a1.x, a1.y, a1.z, a1.w};
        #pragma unroll
        for (int r = 0; r < 8; r++) {
            s[r][0] += av[r] * bv.x;
            s[r][1] += av[r] * bv.y;
            s[r][2] += av[r] * bv.z;
            s[r][3] += av[r] * bv.w;
        }
    }
}

__device__ __forceinline__ void load_tile8(const float* __restrict__ M,
                                           int i0, int j0, float v[8][4])
{
    #pragma unroll
    for (int r = 0; r < 8; r++) {
        const float4 t = *(const float4*)(M + (i0 + r) * LDM + j0);
        v[r][0] = t.x; v[r][1] = t.y; v[r][2] = t.z; v[r][3] = t.w;
    }
}

__device__ __forceinline__ void store_tile8_sym(float* __restrict__ M,
                                                int i0, int j0, bool straddle,
                                                const float v[8][4])
{
    if (!straddle) {
        #pragma unroll
        for (int r = 0; r < 8; r++)
            *(float4*)(M + (i0 + r) * LDM + j0) =
                make_float4(v[r][0], v[r][1], v[r][2], v[r][3]);
        #pragma unroll
        for (int c = 0; c < 4; c++) {
            *(float4*)(M + (j0 + c) * LDM + i0) =
                make_float4(v[0][c], v[1][c], v[2][c], v[3][c]);
            *(float4*)(M + (j0 + c) * LDM + i0 + 4) =
                make_float4(v[4][c], v[5][c], v[6][c], v[7][c]);
        }
    } else {
        #pragma unroll
        for (int r = 0; r < 8; r++)
            #pragma unroll
            for (int c = 0; c < 4; c++) {
                const int i = i0 + r, j = j0 + c;
                if (i <= j) {
                    M[i * LDM + j] = v[r][c];
                    if (i < j) M[j * LDM + i] = v[r][c];
                }
            }
    }
}

__global__ void __launch_bounds__(NTHREADS, 3)
spd_log_cheb_ps11_kernel(const float* __restrict__ xg, float* __restrict__ outg)
{
    extern __shared__ float sm[];
    float* Xs  = sm + 0 * MATN * LDM;   // X -> X~ -> P2
    float* T2s = sm + 1 * MATN * LDM;   // T2
    float* T3s = sm + 2 * MATN * LDM;   // T3 -> b1
    float* Ws  = sm + 3 * MATN * LDM;   // X*X -> W = T4
    float* rs  = sm + 4 * MATN * LDM;   // rowsums + maxima (132 floats)

    const int t = threadIdx.x;
    const float* X = xg + (size_t)blockIdx.x * MATSZ;

    // ---- load X ----
    for (int e = t; e < MATSZ; e += NTHREADS)
        Xs[(e >> 6) * LDM + (e & 63)] = X[e];
    __syncthreads();

    // ---- tile assignment: t < 72 owns 8x4 tile (bi, bj), bj >= 2*bi ----
    const bool active = (t < NTILES);
    int bi = 0, bj = 0;
    {
        int tt = active ? t : 0;
        while (tt >= 16 - 2 * bi) { tt -= 16 - 2 * bi; bi++; }
        bj = 2 * bi + tt;
    }
    const int i0 = bi * 8, j0 = bj * 4;
    const bool straddle = (bj <= 2 * bi + 1);

    // ---- matmul 1: X2 = X * X -> Ws ----
    if (active) {
        float s[8][4];
        mm_tile8(Xs, Xs, i0, j0, s);
        store_tile8_sym(Ws, i0, j0, straddle, s);
    }
    __syncthreads();

    // ---- Gershgorin bounds (X and X^2) ----
    if (t < MATN) {
        float sa = 0.f, sb = 0.f;
        #pragma unroll
        for (int j = 0; j < MATN; j++) {
            sa += fabsf(Xs[t * LDM + j]);
            sb += fabsf(Ws[t * LDM + j]);
        }
        rs[t] = sa;
        rs[64 + t] = sb;
    }
    __syncthreads();
    if (t < 32) {
        float ma = fmaxf(rs[t], rs[t + 32]);
        float mb = fmaxf(rs[64 + t], rs[96 + t]);
        #pragma unroll
        for (int o = 16; o > 0; o >>= 1) {
            ma = fmaxf(ma, __shfl_xor_sync(0xffffffffu, ma, o));
            mb = fmaxf(mb, __shfl_xor_sync(0xffffffffu, mb, o));
        }
        if (t == 0) { rs[128] = ma; rs[129] = mb; }
    }
    __syncthreads();

    // ---- interval, beta, coefficients, PS fold (deg 11, base 4, q<=2) ----
    const float lo = 0.95f;
    float bmax = fminf(rs[128] * 1.0003f + 2e-3f, sqrtf(rs[129] * 1.001f) + 5e-3f);
    bmax = fmaxf(bmax, lo + 0.5f);
    const float cc     = 0.5f * (bmax + lo);
    const float dd     = 0.5f * (bmax - lo);
    const float inv_dd = 1.0f / dd;
    const float inv_d2 = inv_dd * inv_dd;
    const float ratio  = cc * inv_dd;
    const float beta   = ratio - sqrtf(ratio * ratio - 1.0f);

    float a[12];
    a[0] = logf(dd / (2.0f * beta));
    {
        float p = beta;
        a[1] = 2.f * p;
        #pragma unroll
        for (int k = 2; k <= 11; k++) { p = -p * beta; a[k] = 2.f * p / (float)k; }
    }
    float cf[3][4];
    #pragma unroll
    for (int q = 0; q < 3; q++)
        #pragma unroll
        for (int r = 0; r < 4; r++) cf[q][r] = 0.f;
    #pragma unroll
    for (int k = 11; k >= 4; k--) {
        const int q = k >> 2, r = k & 3;
        if (r > 0) { cf[q][r] = 2.f * a[k]; a[4 * q - r] -= a[k]; }
        else       { cf[q][0] = a[k]; }
    }
    #pragma unroll
    for (int r = 0; r < 4; r++) cf[0][r] = a[r];
    // E0 = P0 - P2 coefficients
    const float g0 = cf[0][0] - cf[2][0], g1 = cf[0][1] - cf[2][1];
    const float g2 = cf[0][2] - cf[2][2], g3 = cf[0][3] - cf[2][3];

    // ---- fused elementwise: T2 = (2X^2 - 4cX + 2c^2 I)/d^2 - I ; X~ = (X-c)/d ----
    const float t2diag = 2.f * cc * cc * inv_d2 - 1.f;
    for (int e = t; e < MATSZ; e += NTHREADS) {
        const int r = e >> 6, j = e & 63;
        const int idx = r * LDM + j;
        const float x  = Xs[idx];
        const float x2 = Ws[idx];
        const float dl = (r == j) ? 1.f : 0.f;
        T2s[idx] = (2.f * x2 - 4.f * cc * x) * inv_d2 + t2diag * dl;
        Xs[idx]  = (x - cc * dl) * inv_dd;
    }
    __syncthreads();

    // ---- matmul 2: T3 = 2 X~ T2 - X~ -> T3s ----
    if (active) {
        float s[8][4], xt[8][4];
        mm_tile8(Xs, T2s, i0, j0, s);
        load_tile8(Xs, i0, j0, xt);
        float v[8][4];
        #pragma unroll
        for (int r = 0; r < 8; r++)
            #pragma unroll
            for (int c = 0; c < 4; c++) v[r][c] = 2.f * s[r][c] - xt[r][c];
        store_tile8_sym(T3s, i0, j0, straddle, v);
    }
    __syncthreads();

    // ---- matmul 3: W = 2 X~ T3 - T2 -> Ws ; cache P1, E0 tiles; P2 -> regs ----
    float p1t[8][4], e0t[8][4], p2t[8][4];
    if (active) {
        float s[8][4], xt[8][4], t2[8][4], t3[8][4];
        mm_tile8(Xs, T3s, i0, j0, s);
        load_tile8(Xs, i0, j0, xt);
        load_tile8(T2s, i0, j0, t2);
        load_tile8(T3s, i0, j0, t3);
        float w[8][4];
        #pragma unroll
        for (int r = 0; r < 8; r++)
            #pragma unroll
            for (int c = 0; c < 4; c++) {
                const float dl = ((i0 + r) == (j0 + c)) ? 1.f : 0.f;
                w[r][c]   = 2.f * s[r][c] - t2[r][c];
                p2t[r][c] = cf[2][0] * dl + cf[2][1] * xt[r][c]
                          + cf[2][2] * t2[r][c] + cf[2][3] * t3[r][c];
                p1t[r][c] = cf[1][0] * dl + cf[1][1] * xt[r][c]
                          + cf[1][2] * t2[r][c] + cf[1][3] * t3[r][c];
                e0t[r][c] = g0 * dl + g1 * xt[r][c]
                          + g2 * t2[r][c] + g3 * t3[r][c];
            }
        store_tile8_sym(Ws, i0, j0, straddle, w);   // X2 in Ws has no readers now
    }
    __syncthreads();   // ALL threads: matmul-3 reads of Xs complete
    if (active)
        store_tile8_sym(Xs, i0, j0, straddle, p2t); // P2 overwrites X~
    __syncthreads();

    // ---- matmul 4: b1 = 2 W P2 + P1 -> T3s (T3 dead) ----
    if (active) {
        float s[8][4];
        mm_tile8(Ws, Xs, i0, j0, s);
        float v[8][4];
        #pragma unroll
        for (int r = 0; r < 8; r++)
            #pragma unroll
            for (int c = 0; c < 4; c++)
                v[r][c] = 2.f * s[r][c] + p1t[r][c];
        store_tile8_sym(T3s, i0, j0, straddle, v);
    }
    __syncthreads();

    // ---- matmul 5: S = W b1 + (P0 - P2) -> output ----
    if (active) {
        float s[8][4];
        mm_tile8(Ws, T3s, i0, j0, s);
        float* o = outg + (size_t)blockIdx.x * OUTSZ;
        #pragma unroll
        for (int r = 0; r < 8; r++)
            #pragma unroll
            for (int c = 0; c < 4; c++) {
                const int i = i0 + r, j = j0 + c;
                if (i <= j)
                    o[i * MATN - (i * (i - 1)) / 2 + (j - i)] = s[r][c] + e0t[r][c];
            }
    }
}

extern "C" void kernel_launch(void* const* d_in, const int* in_sizes, int n_in,
                              void* d_out, int out_size)
{
    const float* x = (const float*)d_in[0];
    float* out = (float*)d_out;
    const int B = in_sizes[0] / MATSZ;

    const int smem_bytes = (4 * MATN * LDM + 132) * (int)sizeof(float);
    cudaFuncSetAttribute(spd_log_cheb_ps11_kernel,
                         cudaFuncAttributeMaxDynamicSharedMemorySize, smem_bytes);

    spd_log_cheb_ps11_kernel<<<B, NTHREADS, smem_bytes>>>(x, out);
}

// round 7
// speedup vs baseline: 1.7792x; 1.3954x over previous
#include <cuda_runtime.h>
#include <math.h>

// SPD log-map: Chebyshev deg-8 + Paterson-Stockmeyer, base W = T_3.
//   log spectrum-mapped: sum_{k=0}^{8} a_k T_k(t), a_k = 2(-1)^{k+1} beta^k/k.
//   Fold via T_q(W) T_r = (T_{3q+r} + T_{3q-r})/2 into q<=2:
//     S = (P0 - P2) + W*(P1 + 2*W*P2),  P_q = cf[q][0] I + cf[q][1] X~ + cf[q][2] T2
// 4 matmuls: X*X (-> bound + T2 elementwise), W=T3, W*P2, W*b1.
// 8x4 register tiles over the upper triangle (72 tiles, 96 threads);
// A-operand rows read as contiguous float4 via symmetry (A[i][k]=A[k][i]).
// 3 smem matrix buffers -> 4 CTAs/SM. P1/E0 tiles cached in registers.
// All __syncthreads() reached unconditionally.

#define LDM      68
#define NTHREADS 96
#define NTILES   72
#define MATN     64
#define MATSZ    (MATN * MATN)
#define OUTSZ    2080

__device__ __forceinline__ void mm_tile8(const float* __restrict__ A,
                                         const float* __restrict__ B,
                                         int i0, int j0, float s[8][4])
{
    #pragma unroll
    for (int r = 0; r < 8; r++)
        #pragma unroll
        for (int c = 0; c < 4; c++) s[r][c] = 0.f;
    const float* Ap = A + i0;
    const float* Bp = B + j0;
    #pragma unroll 4
    for (int kk = 0; kk < MATN; kk++) {
        const float4 a0 = *(const float4*)(Ap + kk * LDM);
        const float4 a1 = *(const float4*)(Ap + kk * LDM + 4);
        const float4 bv = *(const float4*)(Bp + kk * LDM);
        const float av[8] = {a0.x, a0.y, a0.z, a0.w, a1.x, a1.y, a1.z, a1.w};
        #pragma unroll
        for (int r = 0; r < 8; r++) {
            s[r][0] += av[r] * bv.x;
            s[r][1] += av[r] * bv.y;
            s[r][2] += av[r] * bv.z;
            s[r][3] += av[r] * bv.w;
        }
    }
}

__device__ __forceinline__ void load_tile8(const float* __restrict__ M,
                                           int i0, int j0, float v[8][4])
{
    #pragma unroll
    for (int r = 0; r < 8; r++) {
        const float4 t = *(const float4*)(M + (i0 + r) * LDM + j0);
        v[r][0] = t.x; v[r][1] = t.y; v[r][2] = t.z; v[r][3] = t.w;
    }
}

__device__ __forceinline__ void store_tile8_sym(float* __restrict__ M,
                                                int i0, int j0, bool straddle,
                                                const float v[8][4])
{
    if (!straddle) {
        #pragma unroll
        for (int r = 0; r < 8; r++)
            *(float4*)(M + (i0 + r) * LDM + j0) =
                make_float4(v[r][0], v[r][1], v[r][2], v[r][3]);
        #pragma unroll
        for (int c = 0; c < 4; c++) {
            *(float4*)(M + (j0 + c) * LDM + i0) =
                make_float4(v[0][c], v[1][c], v[2][c], v[3][c]);
            *(float4*)(M + (j0 + c) * LDM + i0 + 4) =
                make_float4(v[4][c], v[5][c], v[6][c], v[7][c]);
        }
    } else {
        #pragma unroll
        for (int r = 0; r < 8; r++)
            #pragma unroll
            for (int c = 0; c < 4; c++) {
                const int i = i0 + r, j = j0 + c;
                if (i <= j) {
                    M[i * LDM + j] = v[r][c];
                    if (i < j) M[j * LDM + i] = v[r][c];
                }
            }
    }
}

__global__ void __launch_bounds__(NTHREADS, 4)
spd_log_cheb_ps8_kernel(const float* __restrict__ xg, float* __restrict__ outg)
{
    extern __shared__ float sm[];
    float* Xs  = sm + 0 * MATN * LDM;   // X -> X~ -> b1
    float* T2s = sm + 1 * MATN * LDM;   // T2 -> P2
    float* Ws  = sm + 2 * MATN * LDM;   // X*X -> W = T3
    float* rs  = sm + 3 * MATN * LDM;   // rowsums + maxima (132 floats)

    const int t = threadIdx.x;
    const float* X = xg + (size_t)blockIdx.x * MATSZ;

    // ---- load X ----
    for (int e = t; e < MATSZ; e += NTHREADS)
        Xs[(e >> 6) * LDM + (e & 63)] = X[e];
    __syncthreads();

    // ---- tile assignment: t < 72 owns 8x4 tile (bi, bj), bj >= 2*bi ----
    const bool active = (t < NTILES);
    int bi = 0, bj = 0;
    {
        int tt = active ? t : 0;
        while (tt >= 16 - 2 * bi) { tt -= 16 - 2 * bi; bi++; }
        bj = 2 * bi + tt;
    }
    const int i0 = bi * 8, j0 = bj * 4;
    const bool straddle = (bj <= 2 * bi + 1);

    // ---- matmul 1: X2 = X * X -> Ws ----
    if (active) {
        float s[8][4];
        mm_tile8(Xs, Xs, i0, j0, s);
        store_tile8_sym(Ws, i0, j0, straddle, s);
    }
    __syncthreads();

    // ---- Gershgorin bounds (X and X^2) ----
    if (t < MATN) {
        float sa = 0.f, sb = 0.f;
        #pragma unroll
        for (int j = 0; j < MATN; j++) {
            sa += fabsf(Xs[t * LDM + j]);
            sb += fabsf(Ws[t * LDM + j]);
        }
        rs[t] = sa;
        rs[64 + t] = sb;
    }
    __syncthreads();
    if (t < 32) {
        float ma = fmaxf(rs[t], rs[t + 32]);
        float mb = fmaxf(rs[64 + t], rs[96 + t]);
        #pragma unroll
        for (int o = 16; o > 0; o >>= 1) {
            ma = fmaxf(ma, __shfl_xor_sync(0xffffffffu, ma, o));
            mb = fmaxf(mb, __shfl_xor_sync(0xffffffffu, mb, o));
        }
        if (t == 0) { rs[128] = ma; rs[129] = mb; }
    }
    __syncthreads();

    // ---- interval, beta, coefficients, PS fold (deg 8, base 3, q<=2) ----
    const float lo = 0.95f;
    float bmax = fminf(rs[128] * 1.0003f + 2e-3f, sqrtf(rs[129] * 1.001f) + 5e-3f);
    bmax = fmaxf(bmax, lo + 0.5f);
    const float cc     = 0.5f * (bmax + lo);
    const float dd     = 0.5f * (bmax - lo);
    const float inv_dd = 1.0f / dd;
    const float inv_d2 = inv_dd * inv_dd;
    const float ratio  = cc * inv_dd;
    const float beta   = ratio - sqrtf(ratio * ratio - 1.0f);

    float a[9];
    a[0] = logf(dd / (2.0f * beta));
    {
        float p = beta;
        a[1] = 2.f * p;
        #pragma unroll
        for (int k = 2; k <= 8; k++) { p = -p * beta; a[k] = 2.f * p / (float)k; }
    }
    // fold a_k -> cf[q][r] using T_q(W) T_r = (T_{3q+r} + T_{3q-r})/2, W = T_3
    float cf[3][3];
    #pragma unroll
    for (int q = 0; q < 3; q++)
        #pragma unroll
        for (int r = 0; r < 3; r++) cf[q][r] = 0.f;
    #pragma unroll
    for (int k = 8; k >= 3; k--) {
        const int q = k / 3, r = k - 3 * q;
        if (r > 0) { cf[q][r] = 2.f * a[k]; a[3 * q - r] -= a[k]; }
        else       { cf[q][0] = a[k]; }
    }
    #pragma unroll
    for (int r = 0; r < 3; r++) cf[0][r] = a[r];
    // E0 = P0 - P2 coefficients
    const float g0 = cf[0][0] - cf[2][0];
    const float g1 = cf[0][1] - cf[2][1];
    const float g2 = cf[0][2] - cf[2][2];

    // ---- fused elementwise: T2 = (2X^2 - 4cX + 2c^2 I)/d^2 - I ; X~ = (X-c)/d ----
    const float t2diag = 2.f * cc * cc * inv_d2 - 1.f;
    for (int e = t; e < MATSZ; e += NTHREADS) {
        const int r = e >> 6, j = e & 63;
        const int idx = r * LDM + j;
        const float x  = Xs[idx];
        const float x2 = Ws[idx];
        const float dl = (r == j) ? 1.f : 0.f;
        T2s[idx] = (2.f * x2 - 4.f * cc * x) * inv_d2 + t2diag * dl;
        Xs[idx]  = (x - cc * dl) * inv_dd;
    }
    __syncthreads();

    // ---- matmul 2: W = T3 = 2 X~ T2 - X~ -> Ws (X2 dead) ;
    //      cache P1, E0 tiles in regs; P2 tile -> regs then smem ----
    float p1t[8][4], e0t[8][4], p2t[8][4];
    if (active) {
        float s[8][4], xt[8][4], t2[8][4];
        mm_tile8(Xs, T2s, i0, j0, s);
        load_tile8(Xs, i0, j0, xt);
        load_tile8(T2s, i0, j0, t2);
        float w[8][4];
        #pragma unroll
        for (int r = 0; r < 8; r++)
            #pragma unroll
            for (int c = 0; c < 4; c++) {
                const float dl = ((i0 + r) == (j0 + c)) ? 1.f : 0.f;
                w[r][c]   = 2.f * s[r][c] - xt[r][c];
                p2t[r][c] = cf[2][0] * dl + cf[2][1] * xt[r][c] + cf[2][2] * t2[r][c];
                p1t[r][c] = cf[1][0] * dl + cf[1][1] * xt[r][c] + cf[1][2] * t2[r][c];
                e0t[r][c] = g0 * dl + g1 * xt[r][c] + g2 * t2[r][c];
            }
        store_tile8_sym(Ws, i0, j0, straddle, w);   // X2 in Ws has no readers now
    }
    __syncthreads();   // ALL threads: matmul-2 reads of T2s complete
    if (active)
        store_tile8_sym(T2s, i0, j0, straddle, p2t);  // P2 overwrites T2
    __syncthreads();

    // ---- matmul 3: b1 = 2 W P2 + P1 -> Xs (X~ dead) ----
    float b1t[8][4];
    if (active) {
        float s[8][4];
        mm_tile8(Ws, T2s, i0, j0, s);
        #pragma unroll
        for (int r = 0; r < 8; r++)
            #pragma unroll
            for (int c = 0; c < 4; c++)
                b1t[r][c] = 2.f * s[r][c] + p1t[r][c];
    }
    __syncthreads();   // matmul-3 reads of Xs (none) / keep ordering for Xs write
    if (active)
        store_tile8_sym(Xs, i0, j0, straddle, b1t);
    __syncthreads();

    // ---- matmul 4: S = W b1 + (P0 - P2) -> output ----
    if (active) {
        float s[8][4];
        mm_tile8(Ws, Xs, i0, j0, s);
        float* o = outg + (size_t)blockIdx.x * OUTSZ;
        #pragma unroll
        for (int r = 0; r < 8; r++)
            #pragma unroll
            for (int c = 0; c < 4; c++) {
                const int i = i0 + r, j = j0 + c;
                if (i <= j)
                    o[i * MATN - (i * (i - 1)) / 2 + (j - i)] = s[r][c] + e0t[r][c];
            }
    }
}

extern "C" void kernel_launch(void* const* d_in, const int* in_sizes, int n_in,
                              void* d_out, int out_size)
{
    const float* x = (const float*)d_in[0];
    float* out = (float*)d_out;
    const int B = in_sizes[0] / MATSZ;

    const int smem_bytes = (3 * MATN * LDM + 132) * (int)sizeof(float);
    cudaFuncSetAttribute(spd_log_cheb_ps8_kernel,
                         cudaFuncAttributeMaxDynamicSharedMemorySize, smem_bytes);

    spd_log_cheb_ps8_kernel<<<B, NTHREADS, smem_bytes>>>(x, out);
}